// round 16
// baseline (speedup 1.0000x reference)
#include <cuda_runtime.h>

#define DIM   48
#define NBINS 38

#define BIN_LO   3.25f
#define BIN_STEP (17.5f / 37.0f)    // linspace(3.25, 20.75, 38) spacing
#define BIN_INV  (37.0f / 17.5f)

__device__ __forceinline__ int bin_of(float d) {
    int k = (int)rintf((d - BIN_LO) * BIN_INV);
    k = k < 0 ? 0 : (k > NBINS - 1 ? NBINS - 1 : k);
    float best = fabsf(d - fmaf((float)k, BIN_STEP, BIN_LO));
    if (k > 0) {
        float c = fabsf(d - fmaf((float)(k - 1), BIN_STEP, BIN_LO));
        if (c < best) { best = c; k = k - 1; }
    }
    if (k < NBINS - 1) {
        float c = fabsf(d - fmaf((float)(k + 1), BIN_STEP, BIN_LO));
        if (c < best) { k = k + 1; }
    }
    return k;
}

__device__ __forceinline__ void row_stats(const float4& a, const float4& b,
                                          const float4& c, float& mu, float& rs) {
    float sum = a.x + a.y + a.z + a.w
              + b.x + b.y + b.z + b.w
              + c.x + c.y + c.z + c.w;
    float ssq = a.x*a.x + a.y*a.y + a.z*a.z + a.w*a.w
              + b.x*b.x + b.y*b.y + b.z*b.z + b.w*b.w
              + c.x*c.x + c.y*c.y + c.z*c.z + c.w*c.w;
    sum += __shfl_xor_sync(0xffffffffu, sum, 1);
    ssq += __shfl_xor_sync(0xffffffffu, ssq, 1);
    sum += __shfl_xor_sync(0xffffffffu, sum, 2);
    ssq += __shfl_xor_sync(0xffffffffu, ssq, 2);
    mu = sum * (1.0f / DIM);
    const float var = ssq * (1.0f / DIM) - mu * mu;
    rs = rsqrtf(var + 1e-5f);
}

// FINAL — converged optimum (R13, reproduced R15):
// 4 lanes per row, 2 rows per thread — 6 bulk LDG.128 (default caching) +
// x-coord loads all front-batched before any dependent math; smem W+b table;
// 4 blocks/SM (64-reg schedule, RF-bound); __stcs on bulk stores only
// (evict-first full-line writes cut L2 write-allocate pollution against the
// read stream). Pair rows and single-LN rows fused in one grid.
// Measured: 66.0 us, 5.48 TB/s (69% DRAM), rel_err 1.0e-4.
__global__ __launch_bounds__(256, 4) void fused_kernel(
    const float*  __restrict__ x,
    const float4* __restrict__ pair4,
    const float4* __restrict__ single4,
    const float4* __restrict__ W4,
    const float4* __restrict__ b4,
    const float4* __restrict__ gp4,
    const float4* __restrict__ bp4,
    const float4* __restrict__ gm4,
    const float4* __restrict__ bm4,
    float4*       __restrict__ pair_out4,
    float4*       __restrict__ single_out4,
    int L, int total, int blocksP, int lshift)
{
    __shared__ float4 sWb[NBINS * 12];     // W row + bias, folded (7296 B)

    const bool is_pair = (blockIdx.x < blocksP);

    if (is_pair) {
        for (int idx = threadIdx.x; idx < NBINS * 12; idx += 256) {
            float4 w = W4[idx];
            float4 c = b4[idx % 12];
            w.x += c.x; w.y += c.y; w.z += c.z; w.w += c.w;
            sWb[idx] = w;
        }
        __syncthreads();
    }

    const float4* src;
    float4*       dst;
    const float4* g4;
    const float4* be4;
    int r0, limit;
    if (is_pair) {
        r0    = blockIdx.x * 128 + (threadIdx.x >> 2);
        limit = total;
        src = pair4;   dst = pair_out4;   g4 = gp4; be4 = bp4;
    } else {
        r0    = (blockIdx.x - blocksP) * 128 + (threadIdx.x >> 2);
        limit = L;
        src = single4; dst = single_out4; g4 = gm4; be4 = bm4;
    }
    const int r1 = r0 + 64;
    if (r0 >= limit) return;
    const bool live1 = (r1 < limit);

    const int lane4 = threadIdx.x & 3;

    // --- front batch: 6 bulk loads (default caching) ---
    const float4* p0 = src + (size_t)r0 * 12 + lane4;
    const float4* p1 = src + (size_t)r1 * 12 + lane4;
    float4 a0 = p0[0], a1 = p0[4], a2 = p0[8];
    float4 c0 = make_float4(0.f,0.f,0.f,0.f), c1 = c0, c2 = c0;
    if (live1) { c0 = p1[0]; c1 = p1[4]; c2 = p1[8]; }

    // --- distance/bin math before stats: x loads overlap bulk-load wait ---
    const float4* wr0 = sWb;
    const float4* wr1 = sWb;
    bool add_w = false;
    if (is_pair) {
        int i0, j0, i1, j1;
        if (lshift >= 0) {
            i0 = r0 >> lshift; j0 = r0 & (L - 1);
            i1 = r1 >> lshift; j1 = r1 & (L - 1);
        } else {
            i0 = r0 / L; j0 = r0 - i0 * L;
            i1 = r1 / L; j1 = r1 - i1 * L;
        }
        const float dx0 = __ldg(x + 3*i0)     - __ldg(x + 3*j0);
        const float dy0 = __ldg(x + 3*i0 + 1) - __ldg(x + 3*j0 + 1);
        const float dz0 = __ldg(x + 3*i0 + 2) - __ldg(x + 3*j0 + 2);
        const float dx1 = __ldg(x + 3*i1)     - __ldg(x + 3*j1);
        const float dy1 = __ldg(x + 3*i1 + 1) - __ldg(x + 3*j1 + 1);
        const float dz1 = __ldg(x + 3*i1 + 2) - __ldg(x + 3*j1 + 2);
        const int k0 = bin_of(sqrtf(dx0*dx0 + dy0*dy0 + dz0*dz0 + 1e-12f));
        const int k1 = bin_of(sqrtf(dx1*dx1 + dy1*dy1 + dz1*dz1 + 1e-12f));
        wr0 = sWb + k0 * 12 + lane4;
        wr1 = sWb + k1 * 12 + lane4;
        add_w = true;
    }

    // --- stats (consume bulk loads) ---
    float mu0, rs0, mu1, rs1;
    row_stats(a0, a1, a2, mu0, rs0);
    row_stats(c0, c1, c2, mu1, rs1);

    float4* q0 = dst + (size_t)r0 * 12 + lane4;
    float4* q1 = dst + (size_t)r1 * 12 + lane4;

    #pragma unroll
    for (int c = 0; c < 3; c++) {
        const float4 G = g4 [lane4 + 4 * c];
        float4 B0 = be4[lane4 + 4 * c];
        float4 B1 = B0;
        if (add_w) {
            const float4 w0 = wr0[4 * c];
            const float4 w1 = wr1[4 * c];
            B1.x = B0.x + w1.x; B1.y = B0.y + w1.y;
            B1.z = B0.z + w1.z; B1.w = B0.w + w1.w;
            B0.x += w0.x; B0.y += w0.y; B0.z += w0.z; B0.w += w0.w;
        }
        {
            const float4 v = (c == 0) ? a0 : (c == 1) ? a1 : a2;
            float4 o;
            o.x = fmaf((v.x - mu0) * rs0, G.x, B0.x);
            o.y = fmaf((v.y - mu0) * rs0, G.y, B0.y);
            o.z = fmaf((v.z - mu0) * rs0, G.z, B0.z);
            o.w = fmaf((v.w - mu0) * rs0, G.w, B0.w);
            __stcs(q0 + 4 * c, o);
        }
        if (live1) {
            const float4 v = (c == 0) ? c0 : (c == 1) ? c1 : c2;
            float4 o;
            o.x = fmaf((v.x - mu1) * rs1, G.x, B1.x);
            o.y = fmaf((v.y - mu1) * rs1, G.y, B1.y);
            o.z = fmaf((v.z - mu1) * rs1, G.z, B1.z);
            o.w = fmaf((v.w - mu1) * rs1, G.w, B1.w);
            __stcs(q1 + 4 * c, o);
        }
    }
}

// ---------------------------------------------------------------------------
extern "C" void kernel_launch(void* const* d_in, const int* in_sizes, int n_in,
                              void* d_out, int out_size) {
    const float* x      = (const float*)d_in[0];
    const float* single = (const float*)d_in[1];
    const float* pair   = (const float*)d_in[2];
    const float* W      = (const float*)d_in[3];
    const float* b      = (const float*)d_in[4];
    const float* gp     = (const float*)d_in[5];
    const float* bp     = (const float*)d_in[6];
    const float* gm     = (const float*)d_in[7];
    const float* bm     = (const float*)d_in[8];

    const int L = in_sizes[1] / DIM;            // single is [1, L, DIM]
    const int total = L * L;

    float* out        = (float*)d_out;
    float* single_out = out;                     // (single_out, pair_out) concatenated
    float* pair_out   = out + (size_t)L * DIM;

    int lshift = -1;
    if ((L & (L - 1)) == 0) {
        lshift = 0;
        while ((1 << lshift) < L) lshift++;
    }

    // 128 rows per block (256 threads, 4 per row, 2 rows per thread)
    const int blocksP = (total + 127) / 128;
    const int blocksS = (L + 127) / 128;

    fused_kernel<<<blocksP + blocksS, 256>>>(
        x,
        (const float4*)pair, (const float4*)single,
        (const float4*)W, (const float4*)b,
        (const float4*)gp, (const float4*)bp,
        (const float4*)gm, (const float4*)bm,
        (float4*)pair_out, (float4*)single_out,
        L, total, blocksP, lshift);
}

// round 17
// speedup vs baseline: 1.0257x; 1.0257x over previous
#include <cuda_runtime.h>

#define DIM   48
#define NBINS 38

#define BIN_LO   3.25f
#define BIN_STEP (17.5f / 37.0f)    // linspace(3.25, 20.75, 38) spacing
#define BIN_INV  (37.0f / 17.5f)

__device__ __forceinline__ int bin_of(float d) {
    int k = (int)rintf((d - BIN_LO) * BIN_INV);
    k = k < 0 ? 0 : (k > NBINS - 1 ? NBINS - 1 : k);
    float best = fabsf(d - fmaf((float)k, BIN_STEP, BIN_LO));
    if (k > 0) {
        float c = fabsf(d - fmaf((float)(k - 1), BIN_STEP, BIN_LO));
        if (c < best) { best = c; k = k - 1; }
    }
    if (k < NBINS - 1) {
        float c = fabsf(d - fmaf((float)(k + 1), BIN_STEP, BIN_LO));
        if (c < best) { k = k + 1; }
    }
    return k;
}

__device__ __forceinline__ void row_stats(const float4& a, const float4& b,
                                          const float4& c, float& mu, float& rs) {
    float sum = a.x + a.y + a.z + a.w
              + b.x + b.y + b.z + b.w
              + c.x + c.y + c.z + c.w;
    float ssq = a.x*a.x + a.y*a.y + a.z*a.z + a.w*a.w
              + b.x*b.x + b.y*b.y + b.z*b.z + b.w*b.w
              + c.x*c.x + c.y*c.y + c.z*c.z + c.w*c.w;
    sum += __shfl_xor_sync(0xffffffffu, sum, 1);
    ssq += __shfl_xor_sync(0xffffffffu, ssq, 1);
    sum += __shfl_xor_sync(0xffffffffu, sum, 2);
    ssq += __shfl_xor_sync(0xffffffffu, ssq, 2);
    mu = sum * (1.0f / DIM);
    const float var = ssq * (1.0f / DIM) - mu * mu;
    rs = rsqrtf(var + 1e-5f);
}

// FINAL — converged optimum (R13; re-measured R15/R16, spread 66.0-67.6 us =
// run-to-run noise on identical SASS):
// 4 lanes per row, 2 rows per thread — 6 bulk LDG.128 (default caching) +
// x-coord loads all front-batched before any dependent math; smem W+b table;
// 4 blocks/SM (64-reg schedule, RF-bound); __stcs on bulk stores only
// (evict-first full-line writes cut L2 write-allocate pollution against the
// read stream). Pair rows and single-LN rows fused in one grid.
// Measured: 66.0-67.6 us, ~5.4-5.5 TB/s (68-69% DRAM), rel_err 1.0e-4.
__global__ __launch_bounds__(256, 4) void fused_kernel(
    const float*  __restrict__ x,
    const float4* __restrict__ pair4,
    const float4* __restrict__ single4,
    const float4* __restrict__ W4,
    const float4* __restrict__ b4,
    const float4* __restrict__ gp4,
    const float4* __restrict__ bp4,
    const float4* __restrict__ gm4,
    const float4* __restrict__ bm4,
    float4*       __restrict__ pair_out4,
    float4*       __restrict__ single_out4,
    int L, int total, int blocksP, int lshift)
{
    __shared__ float4 sWb[NBINS * 12];     // W row + bias, folded (7296 B)

    const bool is_pair = (blockIdx.x < blocksP);

    if (is_pair) {
        for (int idx = threadIdx.x; idx < NBINS * 12; idx += 256) {
            float4 w = W4[idx];
            float4 c = b4[idx % 12];
            w.x += c.x; w.y += c.y; w.z += c.z; w.w += c.w;
            sWb[idx] = w;
        }
        __syncthreads();
    }

    const float4* src;
    float4*       dst;
    const float4* g4;
    const float4* be4;
    int r0, limit;
    if (is_pair) {
        r0    = blockIdx.x * 128 + (threadIdx.x >> 2);
        limit = total;
        src = pair4;   dst = pair_out4;   g4 = gp4; be4 = bp4;
    } else {
        r0    = (blockIdx.x - blocksP) * 128 + (threadIdx.x >> 2);
        limit = L;
        src = single4; dst = single_out4; g4 = gm4; be4 = bm4;
    }
    const int r1 = r0 + 64;
    if (r0 >= limit) return;
    const bool live1 = (r1 < limit);

    const int lane4 = threadIdx.x & 3;

    // --- front batch: 6 bulk loads (default caching) ---
    const float4* p0 = src + (size_t)r0 * 12 + lane4;
    const float4* p1 = src + (size_t)r1 * 12 + lane4;
    float4 a0 = p0[0], a1 = p0[4], a2 = p0[8];
    float4 c0 = make_float4(0.f,0.f,0.f,0.f), c1 = c0, c2 = c0;
    if (live1) { c0 = p1[0]; c1 = p1[4]; c2 = p1[8]; }

    // --- distance/bin math before stats: x loads overlap bulk-load wait ---
    const float4* wr0 = sWb;
    const float4* wr1 = sWb;
    bool add_w = false;
    if (is_pair) {
        int i0, j0, i1, j1;
        if (lshift >= 0) {
            i0 = r0 >> lshift; j0 = r0 & (L - 1);
            i1 = r1 >> lshift; j1 = r1 & (L - 1);
        } else {
            i0 = r0 / L; j0 = r0 - i0 * L;
            i1 = r1 / L; j1 = r1 - i1 * L;
        }
        const float dx0 = __ldg(x + 3*i0)     - __ldg(x + 3*j0);
        const float dy0 = __ldg(x + 3*i0 + 1) - __ldg(x + 3*j0 + 1);
        const float dz0 = __ldg(x + 3*i0 + 2) - __ldg(x + 3*j0 + 2);
        const float dx1 = __ldg(x + 3*i1)     - __ldg(x + 3*j1);
        const float dy1 = __ldg(x + 3*i1 + 1) - __ldg(x + 3*j1 + 1);
        const float dz1 = __ldg(x + 3*i1 + 2) - __ldg(x + 3*j1 + 2);
        const int k0 = bin_of(sqrtf(dx0*dx0 + dy0*dy0 + dz0*dz0 + 1e-12f));
        const int k1 = bin_of(sqrtf(dx1*dx1 + dy1*dy1 + dz1*dz1 + 1e-12f));
        wr0 = sWb + k0 * 12 + lane4;
        wr1 = sWb + k1 * 12 + lane4;
        add_w = true;
    }

    // --- stats (consume bulk loads) ---
    float mu0, rs0, mu1, rs1;
    row_stats(a0, a1, a2, mu0, rs0);
    row_stats(c0, c1, c2, mu1, rs1);

    float4* q0 = dst + (size_t)r0 * 12 + lane4;
    float4* q1 = dst + (size_t)r1 * 12 + lane4;

    #pragma unroll
    for (int c = 0; c < 3; c++) {
        const float4 G = g4 [lane4 + 4 * c];
        float4 B0 = be4[lane4 + 4 * c];
        float4 B1 = B0;
        if (add_w) {
            const float4 w0 = wr0[4 * c];
            const float4 w1 = wr1[4 * c];
            B1.x = B0.x + w1.x; B1.y = B0.y + w1.y;
            B1.z = B0.z + w1.z; B1.w = B0.w + w1.w;
            B0.x += w0.x; B0.y += w0.y; B0.z += w0.z; B0.w += w0.w;
        }
        {
            const float4 v = (c == 0) ? a0 : (c == 1) ? a1 : a2;
            float4 o;
            o.x = fmaf((v.x - mu0) * rs0, G.x, B0.x);
            o.y = fmaf((v.y - mu0) * rs0, G.y, B0.y);
            o.z = fmaf((v.z - mu0) * rs0, G.z, B0.z);
            o.w = fmaf((v.w - mu0) * rs0, G.w, B0.w);
            __stcs(q0 + 4 * c, o);
        }
        if (live1) {
            const float4 v = (c == 0) ? c0 : (c == 1) ? c1 : c2;
            float4 o;
            o.x = fmaf((v.x - mu1) * rs1, G.x, B1.x);
            o.y = fmaf((v.y - mu1) * rs1, G.y, B1.y);
            o.z = fmaf((v.z - mu1) * rs1, G.z, B1.z);
            o.w = fmaf((v.w - mu1) * rs1, G.w, B1.w);
            __stcs(q1 + 4 * c, o);
        }
    }
}

// ---------------------------------------------------------------------------
extern "C" void kernel_launch(void* const* d_in, const int* in_sizes, int n_in,
                              void* d_out, int out_size) {
    const float* x      = (const float*)d_in[0];
    const float* single = (const float*)d_in[1];
    const float* pair   = (const float*)d_in[2];
    const float* W      = (const float*)d_in[3];
    const float* b      = (const float*)d_in[4];
    const float* gp     = (const float*)d_in[5];
    const float* bp     = (const float*)d_in[6];
    const float* gm     = (const float*)d_in[7];
    const float* bm     = (const float*)d_in[8];

    const int L = in_sizes[1] / DIM;            // single is [1, L, DIM]
    const int total = L * L;

    float* out        = (float*)d_out;
    float* single_out = out;                     // (single_out, pair_out) concatenated
    float* pair_out   = out + (size_t)L * DIM;

    int lshift = -1;
    if ((L & (L - 1)) == 0) {
        lshift = 0;
        while ((1 << lshift) < L) lshift++;
    }

    // 128 rows per block (256 threads, 4 per row, 2 rows per thread)
    const int blocksP = (total + 127) / 128;
    const int blocksS = (L + 127) / 128;

    fused_kernel<<<blocksP + blocksS, 256>>>(
        x,
        (const float4*)pair, (const float4*)single,
        (const float4*)W, (const float4*)b,
        (const float4*)gp, (const float4*)bp,
        (const float4*)gm, (const float4*)bm,
        (float4*)pair_out, (float4*)single_out,
        L, total, blocksP, lshift);
}